// round 2
// baseline (speedup 1.0000x reference)
#include <cuda_runtime.h>
#include <math.h>

// Chamfer loss, B=4, C=3, Np=Ng=8192.
// Register-blocked brute-force pairwise d^2 with simultaneous
// row-min (over gt for each predict) and col-min (over predict for each gt).
// sqrt applied only to final mins (monotonicity).
//
// Per pair: e = fma(-2px,gx, fma(-2py,gy, fma(-2pz,gz, g2)));  d2 = e + p2
//   rowmin tracks e (p2 added at end), colmin tracks e+p2 (= d2).

#define BATCH 4
#define TPQ 128          // predict points per block
#define TGQ 128          // gt points per stage
#define RP 8             // micro-tile rows per thread
#define RG 8             // micro-tile cols per thread
#define NTHREADS 256     // 16 (g=tx) x 16 (p=ty)
#define EPSF 1e-12f

__device__ int   g_colmin[BATCH * 8192];   // float bits (all positive -> int order valid)
__device__ float g_rowsum[BATCH * 128];    // per-block partial row sums

__global__ void init_kernel(int n) {
    int i = blockIdx.x * blockDim.x + threadIdx.x;
    if (i < n) g_colmin[i] = 0x7f7fffff;   // FLT_MAX bits
}

__global__ __launch_bounds__(NTHREADS, 2)
void chamfer_main(const float* __restrict__ P, const float* __restrict__ G, int N) {
    const int b     = blockIdx.y;
    const int pbase = blockIdx.x * TPQ;
    const float* Pb = P + (size_t)b * 3 * N;
    const float* Gb = G + (size_t)b * 3 * N;
    const int tid = threadIdx.x;
    const int tx  = tid & 15;        // g direction
    const int ty  = tid >> 4;        // p direction

    __shared__ float4 sp[TPQ];
    __shared__ float4 sg[TGQ];
    __shared__ float  cbuf[16][TGQ + 1];
    __shared__ float  sred[NTHREADS];

    // Load & transform predict tile: (-2px, -2py, -2pz, |p|^2)
    for (int i = tid; i < TPQ; i += NTHREADS) {
        float px = Pb[pbase + i];
        float py = Pb[N + pbase + i];
        float pz = Pb[2 * N + pbase + i];
        sp[i] = make_float4(-2.f * px, -2.f * py, -2.f * pz,
                            px * px + py * py + pz * pz);
    }
    __syncthreads();

    float pa[RP], pb_[RP], pc[RP], pp2[RP], rowmin[RP];
#pragma unroll
    for (int ii = 0; ii < RP; ii++) {
        float4 v = sp[ty * RP + ii];
        pa[ii] = v.x; pb_[ii] = v.y; pc[ii] = v.z; pp2[ii] = v.w;
        rowmin[ii] = 3.4e38f;
    }

    for (int gs = 0; gs < N; gs += TGQ) {
        // Stage gt chunk into smem: (gx, gy, gz, |g|^2)
        for (int i = tid; i < TGQ; i += NTHREADS) {
            float gx = Gb[gs + i];
            float gy = Gb[N + gs + i];
            float gz = Gb[2 * N + gs + i];
            sg[i] = make_float4(gx, gy, gz, gx * gx + gy * gy + gz * gz);
        }
        __syncthreads();

        float gx[RG], gy[RG], gz[RG], g2[RG], colmin[RG];
#pragma unroll
        for (int jj = 0; jj < RG; jj++) {
            float4 v = sg[jj * 16 + tx];
            gx[jj] = v.x; gy[jj] = v.y; gz[jj] = v.z; g2[jj] = v.w;
            colmin[jj] = 3.4e38f;
        }

#pragma unroll
        for (int ii = 0; ii < RP; ii++) {
#pragma unroll
            for (int jj = 0; jj < RG; jj++) {
                float e = fmaf(pc[ii], gz[jj], g2[jj]);
                e = fmaf(pb_[ii], gy[jj], e);
                e = fmaf(pa[ii], gx[jj], e);
                rowmin[ii] = fminf(rowmin[ii], e);
                colmin[jj] = fminf(colmin[jj], e + pp2[ii]);
            }
        }

        // Column reduce across the 16 ty threads sharing each g column
#pragma unroll
        for (int jj = 0; jj < RG; jj++)
            cbuf[ty][jj * 16 + tx] = colmin[jj];
        __syncthreads();

        if (tid < TGQ) {
            float m = cbuf[0][tid];
#pragma unroll
            for (int t = 1; t < 16; t++) m = fminf(m, cbuf[t][tid]);
            m = fmaxf(m, EPSF);  // clamp (matches ref), keeps value positive for int atomicMin
            atomicMin(&g_colmin[b * N + gs + tid], __float_as_int(m));
        }
        __syncthreads();
    }

    // Row-min reduce ACROSS tx: lanes within a warp differing in the low 4
    // bits share ty and partition the g columns (g index = jj*16 + tx), so
    // xor-shuffle over offsets 1,2,4,8 completes the min over all g.
#pragma unroll
    for (int ii = 0; ii < RP; ii++) {
        float m = rowmin[ii];
#pragma unroll
        for (int off = 1; off < 16; off <<= 1)
            m = fminf(m, __shfl_xor_sync(0xffffffffu, m, off));
        rowmin[ii] = m;
    }

    // Only one lane per (ty, row-group) contributes: tx == 0.
    float rsum = 0.f;
    if (tx == 0) {
#pragma unroll
        for (int ii = 0; ii < RP; ii++)
            rsum += sqrtf(fmaxf(rowmin[ii] + pp2[ii], EPSF));
    }

    sred[tid] = rsum;
    __syncthreads();
    for (int s = NTHREADS / 2; s > 0; s >>= 1) {
        if (tid < s) sred[tid] += sred[tid + s];
        __syncthreads();
    }
    if (tid == 0)
        g_rowsum[b * gridDim.x + blockIdx.x] = sred[0];
}

__global__ void finalize_kernel(float* out, int N, int nblocks) {
    __shared__ float sred[256];
    const int tid = threadIdx.x;
    float s = 0.f;
    const int total = BATCH * N;
    for (int i = tid; i < total; i += 256)
        s += sqrtf(__int_as_float(g_colmin[i]));   // already clamped >= EPS
    for (int i = tid; i < nblocks; i += 256)
        s += g_rowsum[i];
    sred[tid] = s;
    __syncthreads();
    for (int st = 128; st > 0; st >>= 1) {
        if (tid < st) sred[tid] += sred[tid + st];
        __syncthreads();
    }
    if (tid == 0)
        out[0] = sred[0] / (float)(BATCH * 2 * N);   // denom = B*(Np+Ng)
}

extern "C" void kernel_launch(void* const* d_in, const int* in_sizes, int n_in,
                              void* d_out, int out_size) {
    const float* P = (const float*)d_in[0];
    const float* G = (const float*)d_in[1];
    const int N  = in_sizes[0] / (BATCH * 3);   // 8192
    const int nb = N / TPQ;                     // 64 p-tiles per batch

    init_kernel<<<(BATCH * N + 255) / 256, 256>>>(BATCH * N);

    dim3 grid(nb, BATCH);
    chamfer_main<<<grid, NTHREADS>>>(P, G, N);

    finalize_kernel<<<1, 256>>>((float*)d_out, N, BATCH * nb);
}